// round 14
// baseline (speedup 1.0000x reference)
#include <cuda_runtime.h>
#include <cstdint>

#define T_STEPS 2048
#define BATCH   1024
#define INPUT   4
#define HID     10
#define OUTF    4
#define CHUNK   16          // timesteps staged per warp per cp.async chunk
#define BPW     2           // batches per warp (two interleaved chains)
#define WARPS   4
#define BPB     (BPW*WARPS) // 8 batches per block
#define THREADS (WARPS*32)  // 128 -> grid 128, 1 warp per SMSP on 128 SMs

typedef unsigned long long u64;

// 84MB scratch for h history (module-static: no runtime allocation)
__device__ float g_hhist[(size_t)T_STEPS * BATCH * HID];

// ---- Blackwell packed f32x2 helpers ----
__device__ __forceinline__ u64 pk2(float lo, float hi) {
    u64 r; asm("mov.b64 %0, {%1,%2};" : "=l"(r) : "f"(lo), "f"(hi)); return r;
}
__device__ __forceinline__ void up2(u64 v, float& lo, float& hi) {
    asm("mov.b64 {%0,%1}, %2;" : "=f"(lo), "=f"(hi) : "l"(v));
}
__device__ __forceinline__ u64 ffma2(u64 a, u64 b, u64 c) {
    u64 d; asm("fma.rn.f32x2 %0, %1, %2, %3;" : "=l"(d) : "l"(a), "l"(b), "l"(c)); return d;
}
__device__ __forceinline__ u64 fadd2(u64 a, u64 b) {
    u64 d; asm("add.rn.f32x2 %0, %1, %2;" : "=l"(d) : "l"(a), "l"(b)); return d;
}
__device__ __forceinline__ u64 fmul2(u64 a, u64 b) {
    u64 d; asm("mul.rn.f32x2 %0, %1, %2;" : "=l"(d) : "l"(a), "l"(b)); return d;
}

// HW tanh (MUFU)
__device__ __forceinline__ float htanh(float x) {
    float y; asm("tanh.approx.f32 %0, %1;" : "=f"(y) : "f"(x)); return y;
}

__device__ __forceinline__ void cp_async16(void* dst, const void* src) {
    unsigned d = (unsigned)__cvta_generic_to_shared(dst);
    asm volatile("cp.async.ca.shared.global [%0], [%1], 16;\n" :: "r"(d), "l"(src));
}
__device__ __forceinline__ void cp_commit() {
    asm volatile("cp.async.commit_group;\n" ::: "memory");
}
__device__ __forceinline__ void cp_wait1() {
    asm volatile("cp.async.wait_group 1;\n" ::: "memory");
}

// ============================================================================
// Phase 1: recurrence. TWO batches per warp, interleaved chains sharing the
// same weight registers. Lanes 0-15 (role0) own gate pair (i,g); lanes 16-31
// (role1) own (f,o) and also own the c/h state update. Only the product
// p = sigma(i)*tanh(g) crosses the half-warp boundary. h broadcast via shfl
// from lanes 16..25. Warp-autonomous; FC deferred to phase 2 via g_hhist.
// ============================================================================
__global__ void __launch_bounds__(THREADS, 1)
lstm_recurrence_kernel(const float* __restrict__ x,
                       const float* __restrict__ h0,
                       const float* __restrict__ c0,
                       const float* __restrict__ W_ih,
                       const float* __restrict__ W_hh,
                       const float* __restrict__ b_ih,
                       const float* __restrict__ b_hh,
                       float* __restrict__ out,
                       int write_state)
{
    // per-warp private double-buffered x stage: 2 chains * 16 steps * 16B
    __shared__ float4 sx[WARPS][2][BPW][CHUNK];

    const int tid  = threadIdx.x;
    const int warp = tid >> 5;
    const int lane = tid & 31;
    const int role = lane >> 4;                // 0: (i,g) rows, 1: (f,o) rows + c/h
    const int jj   = lane & 15;
    const int j    = (jj < HID) ? jj : (HID - 1);

    const int b0 = blockIdx.x * BPB + warp * BPW;   // chain 0 batch
    const int b1 = b0 + 1;                          // chain 1 batch

    // rows: role0 -> (i=j, g=2H+j); role1 -> (f=H+j, o=3H+j)
    const int r_lo = role ? (HID + j)     : j;
    const int r_hi = role ? (3 * HID + j) : (2 * HID + j);
    // prescale sigmoid gates by 0.5 so sigmoid = 0.5*tanh(acc)+0.5
    const float s_lo = 0.5f;                   // i or f
    const float s_hi = role ? 0.5f : 1.0f;     // o: sigmoid ; g: tanh

    // weights SHARED by both chains
    u64 wih[INPUT], whh[HID], bias2;
#pragma unroll
    for (int k = 0; k < INPUT; k++)
        wih[k] = pk2(W_ih[r_lo * INPUT + k] * s_lo, W_ih[r_hi * INPUT + k] * s_hi);
#pragma unroll
    for (int k = 0; k < HID; k++)
        whh[k] = pk2(W_hh[r_lo * HID + k] * s_lo, W_hh[r_hi * HID + k] * s_hi);
    bias2 = pk2((b_ih[r_lo] + b_hh[r_lo]) * s_lo, (b_ih[r_hi] + b_hh[r_hi]) * s_hi);

    // per-chain state
    u64 hd[BPW][HID];
#pragma unroll
    for (int k = 0; k < HID; k++) {
        const float h0v = h0[b0 * HID + k];
        const float h1v = h0[b1 * HID + k];
        hd[0][k] = pk2(h0v, h0v);
        hd[1][k] = pk2(h1v, h1v);
    }
    float cst[BPW];
    cst[0] = c0[b0 * HID + j];
    cst[1] = c0[b1 * HID + j];
    float hlast[BPW] = {0.0f, 0.0f};

    const float4* x4 = reinterpret_cast<const float4*>(x);

    // prefetch chunk 0: lane fetches timestep jj of chain `role`
    cp_async16(&sx[warp][0][role][jj], x4 + (size_t)jj * BATCH + b0 + role);
    cp_commit();

    const int NCH = T_STEPS / CHUNK;   // 128
    for (int ch = 0; ch < NCH; ch++) {
        if (ch + 1 < NCH) {
            cp_async16(&sx[warp][(ch + 1) & 1][role][jj],
                       x4 + (size_t)((ch + 1) * CHUNK + jj) * BATCH + b0 + role);
        }
        cp_commit();
        cp_wait1();          // this warp's chunk `ch` resident
        __syncwarp();        // visibility warp-wide

        const int buf = ch & 1;
#pragma unroll 2
        for (int s = 0; s < CHUNK; s++) {
            float hn[BPW];
#pragma unroll
            for (int q = 0; q < BPW; q++) {
                const float4 xv = sx[warp][buf][q][s];   // warp-uniform broadcast
                const u64 xd0 = pk2(xv.x, xv.x);
                const u64 xd1 = pk2(xv.y, xv.y);
                const u64 xd2 = pk2(xv.z, xv.z);
                const u64 xd3 = pk2(xv.w, xv.w);

                // x-part (independent of h)
                u64 xc  = ffma2(xd0, wih[0], bias2);
                u64 xc2 = fmul2(xd1, wih[1]);
                xc  = ffma2(xd2, wih[2], xc);
                xc2 = ffma2(xd3, wih[3], xc2);

                // h-part: 4 short accumulator chains + tree combine
                u64 a  = ffma2(hd[q][0], whh[0], xc);
                u64 b  = ffma2(hd[q][1], whh[1], xc2);
                u64 cc = fmul2(hd[q][2], whh[2]);
                u64 dd = fmul2(hd[q][3], whh[3]);
                a  = ffma2(hd[q][4], whh[4], a);
                b  = ffma2(hd[q][5], whh[5], b);
                cc = ffma2(hd[q][6], whh[6], cc);
                dd = ffma2(hd[q][7], whh[7], dd);
                a  = ffma2(hd[q][8], whh[8], a);
                b  = ffma2(hd[q][9], whh[9], b);
                float zlo, zhi;
                up2(fadd2(fadd2(a, cc), fadd2(b, dd)), zlo, zhi);

                const float tlo = htanh(zlo);   // role0: tanh(i/2) ; role1: tanh(f/2)
                const float thi = htanh(zhi);   // role0: tanh(g)   ; role1: tanh(o/2)

                const float sg_lo = fmaf(0.5f, tlo, 0.5f);  // sigma(i) / sigma(f)
                const float sg_hi = fmaf(0.5f, thi, 0.5f);  // (unused) / sigma(o)
                const float p     = sg_lo * thi;            // role0: sigma(i)*tanh(g)

                // ship p to role1 (role1's payload is ignored on role0)
                const float pr = __shfl_xor_sync(0xffffffffu, p, 16);

                // c/h update owned by role1 lanes (sg_lo = sigma(f) there)
                cst[q] = fmaf(sg_lo, cst[q], pr);
                hn[q] = sg_hi * htanh(cst[q]);
            }

            // broadcast both chains' new h from lanes 16..25, re-duplicate
#pragma unroll
            for (int k = 0; k < HID; k++) {
                const float h0k = __shfl_sync(0xffffffffu, hn[0], 16 + k, 32);
                const float h1k = __shfl_sync(0xffffffffu, hn[1], 16 + k, 32);
                hd[0][k] = pk2(h0k, h0k);
                hd[1][k] = pk2(h1k, h1k);
            }

            // record h for the deferred FC pass (role1 lanes own valid hn)
            if (role && jj < HID) {
                const int t = ch * CHUNK + s;
                g_hhist[((size_t)t * BATCH + b0) * HID + jj] = hn[0];
                g_hhist[((size_t)t * BATCH + b1) * HID + jj] = hn[1];
                hlast[0] = hn[0];
                hlast[1] = hn[1];
            }
        }
    }

    // final states (hT, cT) appended after `out` in the flattened pytree
    if (write_state && role && jj < HID) {
        const size_t off = (size_t)T_STEPS * BATCH * OUTF;
        out[off + (size_t)b0 * HID + jj] = hlast[0];
        out[off + (size_t)b1 * HID + jj] = hlast[1];
        out[off + (size_t)BATCH * HID + (size_t)b0 * HID + jj] = cst[0];
        out[off + (size_t)BATCH * HID + (size_t)b1 * HID + jj] = cst[1];
    }
}

// ============================================================================
// Phase 2: out[t*B+b, :] = h[t,b,:] @ W_fc^T + b_fc   (embarrassingly parallel)
// ============================================================================
__global__ void __launch_bounds__(256)
lstm_fc_kernel(const float* __restrict__ W_fc,
               const float* __restrict__ b_fc,
               float* __restrict__ out)
{
    __shared__ float wf[OUTF * HID];
    __shared__ float bf[OUTF];
    if (threadIdx.x < OUTF * HID) wf[threadIdx.x] = W_fc[threadIdx.x];
    if (threadIdx.x < OUTF)       bf[threadIdx.x] = b_fc[threadIdx.x];
    __syncthreads();

    const size_t idx = (size_t)blockIdx.x * blockDim.x + threadIdx.x;  // (t,b) pair
    if (idx >= (size_t)T_STEPS * BATCH) return;

    const float* h = &g_hhist[idx * HID];
    float hv[HID];
    const float2* h2 = reinterpret_cast<const float2*>(h);   // 40B rows -> 8B aligned
#pragma unroll
    for (int k = 0; k < HID / 2; k++) {
        const float2 v = h2[k];
        hv[2 * k] = v.x; hv[2 * k + 1] = v.y;
    }

    float4 r;
    float* rp = reinterpret_cast<float*>(&r);
#pragma unroll
    for (int o = 0; o < OUTF; o++) {
        float acc0 = bf[o], acc1 = 0.0f;
#pragma unroll
        for (int k = 0; k < HID; k += 2) {
            acc0 = fmaf(hv[k],     wf[o * HID + k],     acc0);
            acc1 = fmaf(hv[k + 1], wf[o * HID + k + 1], acc1);
        }
        rp[o] = acc0 + acc1;
    }
    reinterpret_cast<float4*>(out)[idx] = r;
}

extern "C" void kernel_launch(void* const* d_in, const int* in_sizes, int n_in,
                              void* d_out, int out_size) {
    const float* x    = (const float*)d_in[0];
    const float* h0   = (const float*)d_in[1];
    const float* c0   = (const float*)d_in[2];
    const float* W_ih = (const float*)d_in[3];
    const float* W_hh = (const float*)d_in[4];
    const float* b_ih = (const float*)d_in[5];
    const float* b_hh = (const float*)d_in[6];
    const float* W_fc = (const float*)d_in[7];
    const float* b_fc = (const float*)d_in[8];
    float* out = (float*)d_out;

    const long long need_state = (long long)T_STEPS * BATCH * OUTF + 2LL * BATCH * HID;
    const int write_state = (out_size >= need_state) ? 1 : 0;

    lstm_recurrence_kernel<<<BATCH / BPB, THREADS>>>(
        x, h0, c0, W_ih, W_hh, b_ih, b_hh, out, write_state);

    const long long nrows = (long long)T_STEPS * BATCH;
    lstm_fc_kernel<<<(int)((nrows + 255) / 256), 256>>>(W_fc, b_fc, out);
}

// round 17
// speedup vs baseline: 1.3316x; 1.3316x over previous
#include <cuda_runtime.h>
#include <cstdint>

#define T_STEPS 2048
#define BATCH   1024
#define INPUT   4
#define HID     10
#define OUTF    4
#define CHUNK   16          // timesteps staged per warp per cp.async chunk
#define WARPS   4
#define BPB     (WARPS*2)   // 8 batches per block (2 per warp, one per 16-lane half)
#define THREADS (WARPS*32)  // 128 -> grid 128, 1 warp/SMSP on 128 SMs

typedef unsigned long long u64;

// 84MB scratch for h history (module-static: no runtime allocation)
__device__ float g_hhist[(size_t)T_STEPS * BATCH * HID];

// ---- Blackwell packed f32x2 helpers ----
__device__ __forceinline__ u64 pk2(float lo, float hi) {
    u64 r; asm("mov.b64 %0, {%1,%2};" : "=l"(r) : "f"(lo), "f"(hi)); return r;
}
__device__ __forceinline__ void up2(u64 v, float& lo, float& hi) {
    asm("mov.b64 {%0,%1}, %2;" : "=f"(lo), "=f"(hi) : "l"(v));
}
__device__ __forceinline__ u64 ffma2(u64 a, u64 b, u64 c) {
    u64 d; asm("fma.rn.f32x2 %0, %1, %2, %3;" : "=l"(d) : "l"(a), "l"(b), "l"(c)); return d;
}
__device__ __forceinline__ u64 fadd2(u64 a, u64 b) {
    u64 d; asm("add.rn.f32x2 %0, %1, %2;" : "=l"(d) : "l"(a), "l"(b)); return d;
}
__device__ __forceinline__ u64 fmul2(u64 a, u64 b) {
    u64 d; asm("mul.rn.f32x2 %0, %1, %2;" : "=l"(d) : "l"(a), "l"(b)); return d;
}

// HW tanh (MUFU)
__device__ __forceinline__ float htanh(float x) {
    float y; asm("tanh.approx.f32 %0, %1;" : "=f"(y) : "f"(x)); return y;
}

__device__ __forceinline__ void cp_async16(void* dst, const void* src) {
    unsigned d = (unsigned)__cvta_generic_to_shared(dst);
    asm volatile("cp.async.ca.shared.global [%0], [%1], 16;\n" :: "r"(d), "l"(src));
}
__device__ __forceinline__ void cp_commit() {
    asm volatile("cp.async.commit_group;\n" ::: "memory");
}
__device__ __forceinline__ void cp_wait1() {
    asm volatile("cp.async.wait_group 1;\n" ::: "memory");
}

// ============================================================================
// Phase 1: recurrence. One batch per 16-lane half (2 per warp). Each lane
// owns hidden unit j of its half's batch and computes ALL FOUR gate rows via
// two packed f32x2 dots (i,f) and (g,o) -> no cross-half exchange on the
// critical path; the only cross-lane op is the width-16 h broadcast.
// Warp-autonomous: per-warp cp.async x staging, no block syncs in the loop.
// FC deferred to phase 2 via g_hhist.
// ============================================================================
__global__ void __launch_bounds__(THREADS, 1)
lstm_recurrence_kernel(const float* __restrict__ x,
                       const float* __restrict__ h0,
                       const float* __restrict__ c0,
                       const float* __restrict__ W_ih,
                       const float* __restrict__ W_hh,
                       const float* __restrict__ b_ih,
                       const float* __restrict__ b_hh,
                       float* __restrict__ out,
                       int write_state)
{
    // per-warp private double-buffered x stage: 2 halves * 16 steps * 16B
    __shared__ float4 sx[WARPS][2][2][CHUNK];

    const int tid  = threadIdx.x;
    const int warp = tid >> 5;
    const int lane = tid & 31;
    const int half = lane >> 4;        // which batch in the warp
    const int jj   = lane & 15;
    const int j    = (jj < HID) ? jj : (HID - 1);

    const int batch = blockIdx.x * BPB + warp * 2 + half;

    // ---- per-lane weights: pair (i,f) and (g,o); sigmoid rows prescaled 0.5 ----
    u64 wih_if[INPUT], wih_go[INPUT], whh_if[HID], whh_go[HID];
#pragma unroll
    for (int k = 0; k < INPUT; k++) {
        wih_if[k] = pk2(W_ih[(0*HID + j)*INPUT + k] * 0.5f,
                        W_ih[(1*HID + j)*INPUT + k] * 0.5f);
        wih_go[k] = pk2(W_ih[(2*HID + j)*INPUT + k],
                        W_ih[(3*HID + j)*INPUT + k] * 0.5f);
    }
#pragma unroll
    for (int k = 0; k < HID; k++) {
        whh_if[k] = pk2(W_hh[(0*HID + j)*HID + k] * 0.5f,
                        W_hh[(1*HID + j)*HID + k] * 0.5f);
        whh_go[k] = pk2(W_hh[(2*HID + j)*HID + k],
                        W_hh[(3*HID + j)*HID + k] * 0.5f);
    }
    const u64 bias_if = pk2((b_ih[0*HID+j] + b_hh[0*HID+j]) * 0.5f,
                            (b_ih[1*HID+j] + b_hh[1*HID+j]) * 0.5f);
    const u64 bias_go = pk2((b_ih[2*HID+j] + b_hh[2*HID+j]),
                            (b_ih[3*HID+j] + b_hh[3*HID+j]) * 0.5f);

    // ---- state ----
    u64 hd[HID];
#pragma unroll
    for (int k = 0; k < HID; k++) {
        const float hv = h0[batch * HID + k];
        hd[k] = pk2(hv, hv);
    }
    float c = c0[batch * HID + j];
    float hlast = 0.0f;

    const float4* x4 = reinterpret_cast<const float4*>(x);

    // prefetch chunk 0: lane (half, jj) fetches timestep jj for its half's batch
    cp_async16(&sx[warp][0][half][jj], x4 + (size_t)jj * BATCH + batch);
    cp_commit();

    const int NCH = T_STEPS / CHUNK;   // 128
    for (int ch = 0; ch < NCH; ch++) {
        if (ch + 1 < NCH) {
            cp_async16(&sx[warp][(ch + 1) & 1][half][jj],
                       x4 + (size_t)((ch + 1) * CHUNK + jj) * BATCH + batch);
        }
        cp_commit();
        cp_wait1();          // this warp's chunk `ch` resident
        __syncwarp();        // visibility warp-wide

        const int buf = ch & 1;
#pragma unroll 4
        for (int s = 0; s < CHUNK; s++) {
            const float4 xv = sx[warp][buf][half][s];   // per-half uniform broadcast
            const u64 xd0 = pk2(xv.x, xv.x);
            const u64 xd1 = pk2(xv.y, xv.y);
            const u64 xd2 = pk2(xv.z, xv.z);
            const u64 xd3 = pk2(xv.w, xv.w);

            // x-parts (independent of h broadcast)
            u64 aif = ffma2(xd0, wih_if[0], bias_if);
            u64 bif = fmul2(xd1, wih_if[1]);
            u64 ago = ffma2(xd0, wih_go[0], bias_go);
            u64 bgo = fmul2(xd1, wih_go[1]);
            aif = ffma2(xd2, wih_if[2], aif);
            bif = ffma2(xd3, wih_if[3], bif);
            ago = ffma2(xd2, wih_go[2], ago);
            bgo = ffma2(xd3, wih_go[3], bgo);

            // h-parts: 4 accumulator chains per gate-pair (depth 3) + combine
            u64 cif = fmul2(hd[2], whh_if[2]);
            u64 dif = fmul2(hd[3], whh_if[3]);
            u64 cgo = fmul2(hd[2], whh_go[2]);
            u64 dgo = fmul2(hd[3], whh_go[3]);
            aif = ffma2(hd[0], whh_if[0], aif);
            bif = ffma2(hd[1], whh_if[1], bif);
            ago = ffma2(hd[0], whh_go[0], ago);
            bgo = ffma2(hd[1], whh_go[1], bgo);
            aif = ffma2(hd[4], whh_if[4], aif);
            bif = ffma2(hd[5], whh_if[5], bif);
            ago = ffma2(hd[4], whh_go[4], ago);
            bgo = ffma2(hd[5], whh_go[5], bgo);
            cif = ffma2(hd[6], whh_if[6], cif);
            dif = ffma2(hd[7], whh_if[7], dif);
            cgo = ffma2(hd[6], whh_go[6], cgo);
            dgo = ffma2(hd[7], whh_go[7], dgo);
            aif = ffma2(hd[8], whh_if[8], aif);
            bif = ffma2(hd[9], whh_if[9], bif);
            ago = ffma2(hd[8], whh_go[8], ago);
            bgo = ffma2(hd[9], whh_go[9], bgo);

            float zi, zf, zg, zo;
            up2(fadd2(fadd2(aif, cif), fadd2(bif, dif)), zi, zf);
            up2(fadd2(fadd2(ago, cgo), fadd2(bgo, dgo)), zg, zo);

            // 4 independent MUFUs pipeline through the SFU
            const float ti = htanh(zi);
            const float tf = htanh(zf);
            const float tg = htanh(zg);
            const float to = htanh(zo);

            const float ig = fmaf(0.5f, ti, 0.5f);
            const float fg = fmaf(0.5f, tf, 0.5f);
            const float og = fmaf(0.5f, to, 0.5f);

            c = fmaf(fg, c, ig * tg);
            const float hn = og * htanh(c);
            hlast = hn;

            // width-16 broadcast serves each half's own batch; re-duplicate
#pragma unroll
            for (int k = 0; k < HID; k++) {
                const float hk = __shfl_sync(0xffffffffu, hn, k, 16);
                hd[k] = pk2(hk, hk);
            }

            // record h for the deferred FC pass
            if (jj < HID) {
                const int t = ch * CHUNK + s;
                g_hhist[((size_t)t * BATCH + batch) * HID + jj] = hn;
            }
        }
    }

    // final states (hT, cT) appended after `out` in the flattened pytree
    if (write_state && jj < HID) {
        const size_t off = (size_t)T_STEPS * BATCH * OUTF;
        out[off + (size_t)batch * HID + jj] = hlast;
        out[off + (size_t)BATCH * HID + (size_t)batch * HID + jj] = c;
    }
}

// ============================================================================
// Phase 2: out[t*B+b, :] = h[t,b,:] @ W_fc^T + b_fc   (embarrassingly parallel)
// ============================================================================
__global__ void __launch_bounds__(256)
lstm_fc_kernel(const float* __restrict__ W_fc,
               const float* __restrict__ b_fc,
               float* __restrict__ out)
{
    __shared__ float wf[OUTF * HID];
    __shared__ float bf[OUTF];
    if (threadIdx.x < OUTF * HID) wf[threadIdx.x] = W_fc[threadIdx.x];
    if (threadIdx.x < OUTF)       bf[threadIdx.x] = b_fc[threadIdx.x];
    __syncthreads();

    const size_t idx = (size_t)blockIdx.x * blockDim.x + threadIdx.x;  // (t,b) pair
    if (idx >= (size_t)T_STEPS * BATCH) return;

    const float* h = &g_hhist[idx * HID];
    float hv[HID];
    const float2* h2 = reinterpret_cast<const float2*>(h);   // 40B rows -> 8B aligned
#pragma unroll
    for (int k = 0; k < HID / 2; k++) {
        const float2 v = h2[k];
        hv[2 * k] = v.x; hv[2 * k + 1] = v.y;
    }

    float4 r;
    float* rp = reinterpret_cast<float*>(&r);
#pragma unroll
    for (int o = 0; o < OUTF; o++) {
        float acc0 = bf[o], acc1 = 0.0f;
#pragma unroll
        for (int k = 0; k < HID; k += 2) {
            acc0 = fmaf(hv[k],     wf[o * HID + k],     acc0);
            acc1 = fmaf(hv[k + 1], wf[o * HID + k + 1], acc1);
        }
        rp[o] = acc0 + acc1;
    }
    reinterpret_cast<float4*>(out)[idx] = r;
}

extern "C" void kernel_launch(void* const* d_in, const int* in_sizes, int n_in,
                              void* d_out, int out_size) {
    const float* x    = (const float*)d_in[0];
    const float* h0   = (const float*)d_in[1];
    const float* c0   = (const float*)d_in[2];
    const float* W_ih = (const float*)d_in[3];
    const float* W_hh = (const float*)d_in[4];
    const float* b_ih = (const float*)d_in[5];
    const float* b_hh = (const float*)d_in[6];
    const float* W_fc = (const float*)d_in[7];
    const float* b_fc = (const float*)d_in[8];
    float* out = (float*)d_out;

    const long long need_state = (long long)T_STEPS * BATCH * OUTF + 2LL * BATCH * HID;
    const int write_state = (out_size >= need_state) ? 1 : 0;

    lstm_recurrence_kernel<<<BATCH / BPB, THREADS>>>(
        x, h0, c0, W_ih, W_hh, b_ih, b_hh, out, write_state);

    const long long nrows = (long long)T_STEPS * BATCH;
    lstm_fc_kernel<<<(int)((nrows + 255) / 256), 256>>>(W_fc, b_fc, out);
}